// round 10
// baseline (speedup 1.0000x reference)
#include <cuda_runtime.h>
#include <cuda_bf16.h>
#include <math.h>
#include <cstdint>

// Problem constants
#define BB 16
#define NN 512
#define INF_ 256
#define OUTF 256
#define HH 8
#define NET 50

#define TI 32   // i-rows per block (attention)
#define TJ 32   // j-cols per tile
#define IPW 4   // i rows per warp (8 warps)

// Scratch (device globals; no allocation allowed)
__device__ float g_Wh[BB * NN * OUTF];     // 8.4 MB
__device__ float g_s1[BB * NN * HH];
__device__ float g_s2[BB * NN * HH];

// cp.async helpers (LDGSTS on sm_103a)
#define CP_ASYNC16(dst_u32, src) \
    asm volatile("cp.async.cg.shared.global [%0], [%1], 16;\n" :: "r"(dst_u32), "l"(src))
#define CP_COMMIT() asm volatile("cp.async.commit_group;\n")
#define CP_WAIT1()  asm volatile("cp.async.wait_group 1;\n")
#define CP_WAIT0()  asm volatile("cp.async.wait_group 0;\n")

// packed f32x2 FMA (FFMA2 — sm_103a, only reachable via PTX)
#define FMA_F32X2(d, a, b, c) \
    asm("fma.rn.f32x2 %0, %1, %2, %3;" : "=l"(d) : "l"(a), "l"(b), "l"(c))
#define PACK2(d, lo, hi) \
    asm("mov.b64 %0, {%1, %2};" : "=l"(d) : "f"(lo), "f"(hi))
#define UNPACK2(lo, hi, s) \
    asm("mov.b64 {%0, %1}, %2;" : "=f"(lo), "=f"(hi) : "l"(s))
#define LDS_V2U64(q0, q1, addr) \
    asm volatile("ld.shared.v2.u64 {%0, %1}, [%2];" : "=l"(q0), "=l"(q1) : "r"(addr))

// ---------------------------------------------------------------------------
// Kernel A: Wh = x @ W   (M=8192, K=256, N=256). 128x64 tile, 8x4 microtile.
// (At fp32 FMA roofline per R9 ncu — unchanged.)
// ---------------------------------------------------------------------------
__global__ __launch_bounds__(256) void gemm_kernel(const float* __restrict__ x,
                                                   const float* __restrict__ W) {
    __shared__ float sA[16][132];
    __shared__ float sB[16][64];
    int tid = threadIdx.x;
    int row0 = blockIdx.y * 128;
    int col0 = blockIdx.x * 64;
    int tx = tid & 15, ty = tid >> 4;

    int ar = tid >> 2;
    int ac4 = (tid & 3) << 2;
    int br = tid >> 4;
    int bc4 = (tid & 15) << 2;

    float acc0[4][4] = {}, acc1[4][4] = {};
    float4 pa0, pa1, pb;

    pa0 = *(const float4*)(x + (size_t)(row0 + ar) * INF_ + ac4);
    pa1 = *(const float4*)(x + (size_t)(row0 + 64 + ar) * INF_ + ac4);
    pb  = *(const float4*)(W + (size_t)br * OUTF + col0 + bc4);

    for (int kt = 0; kt < 16; kt++) {
        __syncthreads();
        sA[ac4 + 0][ar] = pa0.x; sA[ac4 + 1][ar] = pa0.y;
        sA[ac4 + 2][ar] = pa0.z; sA[ac4 + 3][ar] = pa0.w;
        sA[ac4 + 0][64 + ar] = pa1.x; sA[ac4 + 1][64 + ar] = pa1.y;
        sA[ac4 + 2][64 + ar] = pa1.z; sA[ac4 + 3][64 + ar] = pa1.w;
        *(float4*)&sB[br][bc4] = pb;
        __syncthreads();
        if (kt < 15) {
            int k0 = (kt + 1) * 16;
            pa0 = *(const float4*)(x + (size_t)(row0 + ar) * INF_ + k0 + ac4);
            pa1 = *(const float4*)(x + (size_t)(row0 + 64 + ar) * INF_ + k0 + ac4);
            pb  = *(const float4*)(W + (size_t)(k0 + br) * OUTF + col0 + bc4);
        }
#pragma unroll
        for (int k = 0; k < 16; k++) {
            float4 aL = *(const float4*)(&sA[k][ty << 2]);
            float4 aH = *(const float4*)(&sA[k][64 + (ty << 2)]);
            float4 b  = *(const float4*)(&sB[k][tx << 2]);
            float av[4] = {aL.x, aL.y, aL.z, aL.w};
            float ah[4] = {aH.x, aH.y, aH.z, aH.w};
            float bv[4] = {b.x, b.y, b.z, b.w};
#pragma unroll
            for (int i = 0; i < 4; i++)
#pragma unroll
                for (int j = 0; j < 4; j++) {
                    acc0[i][j] = fmaf(av[i], bv[j], acc0[i][j]);
                    acc1[i][j] = fmaf(ah[i], bv[j], acc1[i][j]);
                }
        }
    }
#pragma unroll
    for (int i = 0; i < 4; i++) {
        float4 v0 = make_float4(acc0[i][0], acc0[i][1], acc0[i][2], acc0[i][3]);
        float4 v1 = make_float4(acc1[i][0], acc1[i][1], acc1[i][2], acc1[i][3]);
        *(float4*)(g_Wh + (size_t)(row0 + (ty << 2) + i) * OUTF + col0 + (tx << 2)) = v0;
        *(float4*)(g_Wh + (size_t)(row0 + 64 + (ty << 2) + i) * OUTF + col0 + (tx << 2)) = v1;
    }
}

// ---------------------------------------------------------------------------
// Kernel B: s1/s2 projections. One thread per (n,h).
// ---------------------------------------------------------------------------
__global__ __launch_bounds__(256) void s_kernel(const float* __restrict__ a1,
                                                const float* __restrict__ a2) {
    int t = blockIdx.x * blockDim.x + threadIdx.x;
    if (t >= BB * NN * HH) return;
    int h = t & 7;
    int n = t >> 3;
    const float4* row = (const float4*)(g_Wh + (size_t)n * OUTF + h * 32);
    const float4* A1 = (const float4*)a1;
    const float4* A2 = (const float4*)a2;
    float t1 = 0.f, t2 = 0.f;
#pragma unroll
    for (int d4 = 0; d4 < 8; d4++) {
        float4 v = row[d4];
        float4 w1 = A1[d4];
        float4 w2 = A2[d4];
        t1 = fmaf(v.x, w1.x, t1); t1 = fmaf(v.y, w1.y, t1);
        t1 = fmaf(v.z, w1.z, t1); t1 = fmaf(v.w, w1.w, t1);
        t2 = fmaf(v.x, w2.x, t2); t2 = fmaf(v.y, w2.y, t2);
        t2 = fmaf(v.z, w2.z, t2); t2 = fmaf(v.w, w2.w, t2);
    }
    g_s1[t] = t1;
    g_s2[t] = t2;
}

// ---------------------------------------------------------------------------
// Kernel C: fused attention. sP layout now [w][h][j][ii] so the accumulate
// phase reads p via one 16B broadcast (ld.shared.v2.u64) feeding FFMA2 pairs.
// ---------------------------------------------------------------------------
#define SM_WH   0                   // 2 x 8192 f (double-buffered Wh tiles)
#define SM_P    16384               // 8192 f  (p: [warp][h][j][ii])
#define SM_S2   24576               // 288 f   (32 x stride 9)
#define SM_S1   24864               // 256 f
#define SM_EMB  25120               // 450 f   (50 x stride 9)
#define SM_ADJ  25572               // 1024 i  (16B aligned)
#define SM_ET   26596               // 1024 i  (16B aligned)
#define SMEM_FLOATS 27620
#define SMEM_BYTES (SMEM_FLOATS * 4)    // 110480 B -> 2 blocks/SM

__global__ __launch_bounds__(256, 2)
void attn_kernel(const int* __restrict__ adj, const int* __restrict__ et,
                 const float* __restrict__ emb, const float* __restrict__ gamma,
                 const float* __restrict__ beta, float* __restrict__ out) {
    extern __shared__ float sm[];
    float* sWh  = sm + SM_WH;       // [2][8192]
    float* sP   = sm + SM_P;
    float* sS2  = sm + SM_S2;
    float* sS1  = sm + SM_S1;
    float* sEmb = sm + SM_EMB;
    int*   sAdj = (int*)(sm + SM_ADJ);
    int*   sEt  = (int*)(sm + SM_ET);

    int tid = threadIdx.x;
    int w = tid >> 5, ln = tid & 31;
    int b  = blockIdx.x >> 4;
    int i0 = (blockIdx.x & 15) * TI;

    sS1[tid] = g_s1[(size_t)(b * NN + i0) * HH + tid];
    for (int q = tid; q < NET * HH; q += 256)
        sEmb[(q >> 3) * 9 + (q & 7)] = emb[q];

    const float* gWhB = g_Wh + (size_t)b * NN * OUTF;
    unsigned int swhAddr = (unsigned int)__cvta_generic_to_shared(sWh);
    unsigned int spAddr  = (unsigned int)__cvta_generic_to_shared(sP + (w << 10));

    // prologue: async-load Wh tile 0 into buffer 0
#pragma unroll
    for (int q = 0; q < 8; q++) {
        unsigned int off = (unsigned int)(q * 256 + tid) * 16u;
        CP_ASYNC16(swhAddr + off, (const char*)gWhB + off);
    }
    CP_COMMIT();

    // prefetch adj/et/s2 for tile 0 into registers
    int tr  = tid >> 3;
    int tc4 = (tid & 7) << 2;
    int4 adjR = *(const int4*)(adj + (size_t)(b * NN + i0 + tr) * NN + tc4);
    int4 etR  = *(const int4*)(et  + (size_t)(b * NN + i0 + tr) * NN + tc4);
    float s2R = g_s2[(size_t)b * NN * HH + tid];

    unsigned long long acc01[HH], acc23[HH];   // f32x2 accumulators (ii pairs)
    float lsum[IPW][HH];
#pragma unroll
    for (int h = 0; h < HH; h++) { acc01[h] = 0ull; acc23[h] = 0ull; }
#pragma unroll
    for (int ii = 0; ii < IPW; ii++)
#pragma unroll
        for (int h = 0; h < HH; h++) lsum[ii][h] = 0.f;

    for (int jt = 0; jt < NN / TJ; jt++) {
        int cur = jt & 1;
        __syncthreads();
        *(int4*)(sAdj + tr * 32 + tc4) = adjR;
        *(int4*)(sEt  + tr * 32 + tc4) = etR;
        sS2[(tid >> 3) * 9 + (tid & 7)] = s2R;
        if (jt < 15) {
            unsigned int dstBase = swhAddr + (unsigned int)(cur ^ 1) * 32768u;
            const char* srcBase = (const char*)gWhB + (size_t)(jt + 1) * 32768u;
#pragma unroll
            for (int q = 0; q < 8; q++) {
                unsigned int off = (unsigned int)(q * 256 + tid) * 16u;
                CP_ASYNC16(dstBase + off, srcBase + off);
            }
            CP_COMMIT();
            CP_WAIT1();
        } else {
            CP_WAIT0();
        }
        __syncthreads();
        if (jt < 15) {
            int j0n = (jt + 1) * TJ;
            adjR = *(const int4*)(adj + (size_t)(b * NN + i0 + tr) * NN + j0n + tc4);
            etR  = *(const int4*)(et  + (size_t)(b * NN + i0 + tr) * NN + j0n + tc4);
            s2R  = g_s2[(size_t)b * NN * HH + j0n * HH + tid];
        }

        // -------- score phase: lane = j; sP[w][h][j=ln][ii] --------
#pragma unroll
        for (int ii = 0; ii < IPW; ii++) {
            int il = (w << 2) + ii;
            int adjv = sAdj[(il << 5) + ln];
            int eb   = sEt[(il << 5) + ln] * 9;
            const float* s1p = sS1 + (il << 3);
            float* pdst = sP + (w << 10) + (ln << 2) + ii;   // + h*128
#pragma unroll
            for (int h = 0; h < HH; h++) {
                float e = s1p[h] + sS2[ln * 9 + h] + sEmb[eb + h];
                e = fmaf(0.2f, fminf(e, 0.f), fmaxf(e, 0.f));   // leaky relu 0.2
                float p = (adjv != 0) ? __expf(e) : 0.0f;
                lsum[ii][h] += p;
                pdst[h << 7] = p;
            }
        }
        __syncwarp();   // sP region is warp-private

        // -------- accumulate phase: lane = d; FFMA2 over ii pairs --------
        const float* whB = sWh + cur * 8192;
#pragma unroll
        for (int h = 0; h < HH; h++) {
            const float* whc = whB + (h << 5) + ln;
            unsigned int rowA = spAddr + (unsigned int)(h << 9);  // h*128 floats
#pragma unroll 4
            for (int j = 0; j < 32; j++) {
                unsigned long long q01, q23, ww;
                LDS_V2U64(q01, q23, rowA + (unsigned int)(j << 4));
                float wv = whc[j * OUTF];
                PACK2(ww, wv, wv);
                FMA_F32X2(acc01[h], q01, ww, acc01[h]);
                FMA_F32X2(acc23[h], q23, ww, acc23[h]);
            }
        }
    }

    // unpack f32x2 accumulators
    float acc[IPW][HH];
#pragma unroll
    for (int h = 0; h < HH; h++) {
        UNPACK2(acc[0][h], acc[1][h], acc01[h]);
        UNPACK2(acc[2][h], acc[3][h], acc23[h]);
    }

    // -------- softmax denominators (reduce over lanes = j) --------
#pragma unroll
    for (int ii = 0; ii < IPW; ii++)
#pragma unroll
        for (int h = 0; h < HH; h++) {
            float v = lsum[ii][h];
            v += __shfl_xor_sync(0xffffffffu, v, 16);
            v += __shfl_xor_sync(0xffffffffu, v, 8);
            v += __shfl_xor_sync(0xffffffffu, v, 4);
            v += __shfl_xor_sync(0xffffffffu, v, 2);
            v += __shfl_xor_sync(0xffffffffu, v, 1);
            lsum[ii][h] = 1.0f / v;
        }

    float gr[HH], br[HH];
#pragma unroll
    for (int h = 0; h < HH; h++) {
        gr[h] = gamma[(h << 5) + ln];
        br[h] = beta[(h << 5) + ln];
    }

    // -------- LayerNorm + ELU + store --------
    int ibase = b * NN + i0 + (w << 2);
#pragma unroll
    for (int ii = 0; ii < IPW; ii++) {
        float y[HH];
        float s = 0.f;
#pragma unroll
        for (int h = 0; h < HH; h++) { y[h] = acc[ii][h] * lsum[ii][h]; s += y[h]; }
        s += __shfl_xor_sync(0xffffffffu, s, 16);
        s += __shfl_xor_sync(0xffffffffu, s, 8);
        s += __shfl_xor_sync(0xffffffffu, s, 4);
        s += __shfl_xor_sync(0xffffffffu, s, 2);
        s += __shfl_xor_sync(0xffffffffu, s, 1);
        float mu = s * 0.00390625f;   // /256
        float vs = 0.f;
#pragma unroll
        for (int h = 0; h < HH; h++) { float d = y[h] - mu; vs = fmaf(d, d, vs); }
        vs += __shfl_xor_sync(0xffffffffu, vs, 16);
        vs += __shfl_xor_sync(0xffffffffu, vs, 8);
        vs += __shfl_xor_sync(0xffffffffu, vs, 4);
        vs += __shfl_xor_sync(0xffffffffu, vs, 2);
        vs += __shfl_xor_sync(0xffffffffu, vs, 1);
        float rstd = rsqrtf(vs * 0.00390625f + 1e-5f);
        float* op = out + (size_t)(ibase + ii) * OUTF;
#pragma unroll
        for (int h = 0; h < HH; h++) {
            float o = fmaf((y[h] - mu) * rstd, gr[h], br[h]);
            o = (o > 0.f) ? o : expm1f(o);
            op[(h << 5) + ln] = o;
        }
    }
}

// ---------------------------------------------------------------------------
extern "C" void kernel_launch(void* const* d_in, const int* in_sizes, int n_in,
                              void* d_out, int out_size) {
    const float* x     = (const float*)d_in[0];
    const int*   adj   = (const int*)  d_in[1];
    const int*   etyp  = (const int*)  d_in[2];
    const float* W     = (const float*)d_in[3];
    const float* a1    = (const float*)d_in[4];
    const float* a2    = (const float*)d_in[5];
    const float* emb   = (const float*)d_in[6];
    const float* gamma = (const float*)d_in[7];
    const float* beta  = (const float*)d_in[8];
    float* out = (float*)d_out;

    dim3 gg(OUTF / 64, (BB * NN) / 128);
    gemm_kernel<<<gg, 256>>>(x, W);
    s_kernel<<<(BB * NN * HH + 255) / 256, 256>>>(a1, a2);
    cudaFuncSetAttribute(attn_kernel, cudaFuncAttributeMaxDynamicSharedMemorySize, SMEM_BYTES);
    attn_kernel<<<BB * (NN / TI), 256, SMEM_BYTES>>>(adj, etyp, emb, gamma, beta, out);
}

// round 14
// speedup vs baseline: 1.0589x; 1.0589x over previous
#include <cuda_runtime.h>
#include <cuda_bf16.h>
#include <math.h>
#include <cstdint>

// Problem constants
#define BB 16
#define NN 512
#define INF_ 256
#define OUTF 256
#define HH 8
#define NET 50

#define TI 32   // i-rows per block (attention)
#define TJ 32   // j-cols per tile
#define IPW 4   // i rows per warp (8 warps)

// Scratch (device globals; no allocation allowed)
__device__ float g_Wh[BB * NN * OUTF];     // 8.4 MB
__device__ float g_s1[BB * NN * HH];
__device__ float g_s2[BB * NN * HH];

// cp.async helpers (LDGSTS on sm_103a)
#define CP_ASYNC16(dst_u32, src) \
    asm volatile("cp.async.cg.shared.global [%0], [%1], 16;\n" :: "r"(dst_u32), "l"(src))
#define CP_COMMIT() asm volatile("cp.async.commit_group;\n")
#define CP_WAIT1()  asm volatile("cp.async.wait_group 1;\n")
#define CP_WAIT0()  asm volatile("cp.async.wait_group 0;\n")

// packed f32x2 FMA (FFMA2 — sm_103a, only reachable via PTX)
#define FMA_F32X2(d, a, b, c) \
    asm("fma.rn.f32x2 %0, %1, %2, %3;" : "=l"(d) : "l"(a), "l"(b), "l"(c))
#define PACK2(d, lo, hi) \
    asm("mov.b64 %0, {%1, %2};" : "=l"(d) : "f"(lo), "f"(hi))
#define UNPACK2(lo, hi, s) \
    asm("mov.b64 {%0, %1}, %2;" : "=f"(lo), "=f"(hi) : "l"(s))
#define LDS_V2U64(q0, q1, addr) \
    asm volatile("ld.shared.v2.u64 {%0, %1}, [%2];" : "=l"(q0), "=l"(q1) : "r"(addr))

// ---------------------------------------------------------------------------
// Kernel A: Wh = x @ W   (M=8192, K=256, N=256). 128x64 tile, 8x4 microtile.
// At fp32 FMA roofline (R9/R10 ncu) — unchanged.
// ---------------------------------------------------------------------------
__global__ __launch_bounds__(256) void gemm_kernel(const float* __restrict__ x,
                                                   const float* __restrict__ W) {
    __shared__ float sA[16][132];
    __shared__ float sB[16][64];
    int tid = threadIdx.x;
    int row0 = blockIdx.y * 128;
    int col0 = blockIdx.x * 64;
    int tx = tid & 15, ty = tid >> 4;

    int ar = tid >> 2;
    int ac4 = (tid & 3) << 2;
    int br = tid >> 4;
    int bc4 = (tid & 15) << 2;

    float acc0[4][4] = {}, acc1[4][4] = {};
    float4 pa0, pa1, pb;

    pa0 = *(const float4*)(x + (size_t)(row0 + ar) * INF_ + ac4);
    pa1 = *(const float4*)(x + (size_t)(row0 + 64 + ar) * INF_ + ac4);
    pb  = *(const float4*)(W + (size_t)br * OUTF + col0 + bc4);

    for (int kt = 0; kt < 16; kt++) {
        __syncthreads();
        sA[ac4 + 0][ar] = pa0.x; sA[ac4 + 1][ar] = pa0.y;
        sA[ac4 + 2][ar] = pa0.z; sA[ac4 + 3][ar] = pa0.w;
        sA[ac4 + 0][64 + ar] = pa1.x; sA[ac4 + 1][64 + ar] = pa1.y;
        sA[ac4 + 2][64 + ar] = pa1.z; sA[ac4 + 3][64 + ar] = pa1.w;
        *(float4*)&sB[br][bc4] = pb;
        __syncthreads();
        if (kt < 15) {
            int k0 = (kt + 1) * 16;
            pa0 = *(const float4*)(x + (size_t)(row0 + ar) * INF_ + k0 + ac4);
            pa1 = *(const float4*)(x + (size_t)(row0 + 64 + ar) * INF_ + k0 + ac4);
            pb  = *(const float4*)(W + (size_t)(k0 + br) * OUTF + col0 + bc4);
        }
#pragma unroll
        for (int k = 0; k < 16; k++) {
            float4 aL = *(const float4*)(&sA[k][ty << 2]);
            float4 aH = *(const float4*)(&sA[k][64 + (ty << 2)]);
            float4 b  = *(const float4*)(&sB[k][tx << 2]);
            float av[4] = {aL.x, aL.y, aL.z, aL.w};
            float ah[4] = {aH.x, aH.y, aH.z, aH.w};
            float bv[4] = {b.x, b.y, b.z, b.w};
#pragma unroll
            for (int i = 0; i < 4; i++)
#pragma unroll
                for (int j = 0; j < 4; j++) {
                    acc0[i][j] = fmaf(av[i], bv[j], acc0[i][j]);
                    acc1[i][j] = fmaf(ah[i], bv[j], acc1[i][j]);
                }
        }
    }
#pragma unroll
    for (int i = 0; i < 4; i++) {
        float4 v0 = make_float4(acc0[i][0], acc0[i][1], acc0[i][2], acc0[i][3]);
        float4 v1 = make_float4(acc1[i][0], acc1[i][1], acc1[i][2], acc1[i][3]);
        *(float4*)(g_Wh + (size_t)(row0 + (ty << 2) + i) * OUTF + col0 + (tx << 2)) = v0;
        *(float4*)(g_Wh + (size_t)(row0 + 64 + (ty << 2) + i) * OUTF + col0 + (tx << 2)) = v1;
    }
}

// ---------------------------------------------------------------------------
// Kernel B: s1/s2 projections. One thread per (n,h).
// ---------------------------------------------------------------------------
__global__ __launch_bounds__(256) void s_kernel(const float* __restrict__ a1,
                                                const float* __restrict__ a2) {
    int t = blockIdx.x * blockDim.x + threadIdx.x;
    if (t >= BB * NN * HH) return;
    int h = t & 7;
    int n = t >> 3;
    const float4* row = (const float4*)(g_Wh + (size_t)n * OUTF + h * 32);
    const float4* A1 = (const float4*)a1;
    const float4* A2 = (const float4*)a2;
    float t1 = 0.f, t2 = 0.f;
#pragma unroll
    for (int d4 = 0; d4 < 8; d4++) {
        float4 v = row[d4];
        float4 w1 = A1[d4];
        float4 w2 = A2[d4];
        t1 = fmaf(v.x, w1.x, t1); t1 = fmaf(v.y, w1.y, t1);
        t1 = fmaf(v.z, w1.z, t1); t1 = fmaf(v.w, w1.w, t1);
        t2 = fmaf(v.x, w2.x, t2); t2 = fmaf(v.y, w2.y, t2);
        t2 = fmaf(v.z, w2.z, t2); t2 = fmaf(v.w, w2.w, t2);
    }
    g_s1[t] = t1;
    g_s2[t] = t2;
}

// ---------------------------------------------------------------------------
// Kernel C: fused attention. h-outer interleave: score(h) -> STS.128 (conflict
// free) -> syncwarp -> FFMA2 accumulate(h). sP: 2-slot (h parity) buffer,
// 128 floats per slot, 256 floats per warp (matches allocation — R11 overran).
// ---------------------------------------------------------------------------
#define SM_WH   0                   // 2 x 8192 f (double-buffered Wh tiles)
#define SM_P    16384               // 8 warps x 2 slots x 32j x 4ii = 2048 f
#define SM_S2   18432               // 288 f (32 x stride 9)
#define SM_S1   18720               // 256 f
#define SM_EMB  18976               // 450 f (50 x stride 9)
#define SM_ADJ  19428               // 1024 i (19428*4 % 16 == 0)
#define SM_ET   20452               // 1024 i (20452*4 % 16 == 0)
#define SMEM_FLOATS 21476
#define SMEM_BYTES (SMEM_FLOATS * 4)    // 85904 B -> 2 blocks/SM

__global__ __launch_bounds__(256, 2)
void attn_kernel(const int* __restrict__ adj, const int* __restrict__ et,
                 const float* __restrict__ emb, const float* __restrict__ gamma,
                 const float* __restrict__ beta, float* __restrict__ out) {
    extern __shared__ float sm[];
    float* sWh  = sm + SM_WH;       // [2][8192]
    float* sP   = sm + SM_P;        // [w][slot][j][ii]: 256 f per warp
    float* sS2  = sm + SM_S2;
    float* sS1  = sm + SM_S1;
    float* sEmb = sm + SM_EMB;
    int*   sAdj = (int*)(sm + SM_ADJ);
    int*   sEt  = (int*)(sm + SM_ET);

    int tid = threadIdx.x;
    int w = tid >> 5, ln = tid & 31;
    int b  = blockIdx.x >> 4;
    int i0 = (blockIdx.x & 15) * TI;

    sS1[tid] = g_s1[(size_t)(b * NN + i0) * HH + tid];
    for (int q = tid; q < NET * HH; q += 256)
        sEmb[(q >> 3) * 9 + (q & 7)] = emb[q];

    const float* gWhB = g_Wh + (size_t)b * NN * OUTF;
    unsigned int swhAddr = (unsigned int)__cvta_generic_to_shared(sWh);
    float* sPw = sP + (w << 8);                        // 256 floats per warp
    unsigned int spAddr = (unsigned int)__cvta_generic_to_shared(sPw);

    // prologue: async-load Wh tile 0 into buffer 0
#pragma unroll
    for (int q = 0; q < 8; q++) {
        unsigned int off = (unsigned int)(q * 256 + tid) * 16u;
        CP_ASYNC16(swhAddr + off, (const char*)gWhB + off);
    }
    CP_COMMIT();

    // prefetch adj/et/s2 for tile 0 into registers
    int tr  = tid >> 3;
    int tc4 = (tid & 7) << 2;
    int4 adjR = *(const int4*)(adj + (size_t)(b * NN + i0 + tr) * NN + tc4);
    int4 etR  = *(const int4*)(et  + (size_t)(b * NN + i0 + tr) * NN + tc4);
    float s2R = g_s2[(size_t)b * NN * HH + tid];

    unsigned long long acc01[HH], acc23[HH];   // f32x2 accumulators (ii pairs)
    float lsum[IPW][HH];
#pragma unroll
    for (int h = 0; h < HH; h++) { acc01[h] = 0ull; acc23[h] = 0ull; }
#pragma unroll
    for (int ii = 0; ii < IPW; ii++)
#pragma unroll
        for (int h = 0; h < HH; h++) lsum[ii][h] = 0.f;

    for (int jt = 0; jt < NN / TJ; jt++) {
        int cur = jt & 1;
        __syncthreads();
        *(int4*)(sAdj + tr * 32 + tc4) = adjR;
        *(int4*)(sEt  + tr * 32 + tc4) = etR;
        sS2[(tid >> 3) * 9 + (tid & 7)] = s2R;
        if (jt < 15) {
            unsigned int dstBase = swhAddr + (unsigned int)(cur ^ 1) * 32768u;
            const char* srcBase = (const char*)gWhB + (size_t)(jt + 1) * 32768u;
#pragma unroll
            for (int q = 0; q < 8; q++) {
                unsigned int off = (unsigned int)(q * 256 + tid) * 16u;
                CP_ASYNC16(dstBase + off, srcBase + off);
            }
            CP_COMMIT();
            CP_WAIT1();
        } else {
            CP_WAIT0();
        }
        __syncthreads();
        if (jt < 15) {
            int j0n = (jt + 1) * TJ;
            adjR = *(const int4*)(adj + (size_t)(b * NN + i0 + tr) * NN + j0n + tc4);
            etR  = *(const int4*)(et  + (size_t)(b * NN + i0 + tr) * NN + j0n + tc4);
            s2R  = g_s2[(size_t)b * NN * HH + j0n * HH + tid];
        }

        // hoist per-tile: adjacency + emb row per ii (lane = j)
        int adjv[IPW], ebi[IPW];
#pragma unroll
        for (int ii = 0; ii < IPW; ii++) {
            int il = (w << 2) + ii;
            adjv[ii] = sAdj[(il << 5) + ln];
            ebi[ii]  = sEt[(il << 5) + ln] * 9;
        }

        const float* whB = sWh + cur * 8192;
#pragma unroll
        for (int h = 0; h < HH; h++) {
            // -------- score (lane = j): p[4] in regs, one STS.128 --------
            float s2v = sS2[ln * 9 + h];
            float pv[IPW];
#pragma unroll
            for (int ii = 0; ii < IPW; ii++) {
                int il = (w << 2) + ii;
                float e = sS1[(il << 3) + h] + s2v + sEmb[ebi[ii] + h];
                e = fmaf(0.2f, fminf(e, 0.f), fmaxf(e, 0.f));   // leaky relu 0.2
                float p = (adjv[ii] != 0) ? __expf(e) : 0.0f;   // |e|<~12: safe
                lsum[ii][h] += p;
                pv[ii] = p;
            }
            *(float4*)(sPw + ((h & 1) << 7) + (ln << 2)) =
                make_float4(pv[0], pv[1], pv[2], pv[3]);
            __syncwarp();   // cross-lane RAW on sP slot

            // -------- accumulate (lane = d): FFMA2 over ii pairs --------
            const float* whc = whB + (h << 5) + ln;
            unsigned int rowA = spAddr + (unsigned int)((h & 1) << 9);
#pragma unroll 8
            for (int j = 0; j < 32; j++) {
                unsigned long long q01, q23, ww;
                LDS_V2U64(q01, q23, rowA + (unsigned int)(j << 4));
                float wv = whc[j * OUTF];
                PACK2(ww, wv, wv);
                FMA_F32X2(acc01[h], q01, ww, acc01[h]);
                FMA_F32X2(acc23[h], q23, ww, acc23[h]);
            }
        }
    }

    // unpack f32x2 accumulators
    float acc[IPW][HH];
#pragma unroll
    for (int h = 0; h < HH; h++) {
        UNPACK2(acc[0][h], acc[1][h], acc01[h]);
        UNPACK2(acc[2][h], acc[3][h], acc23[h]);
    }

    // -------- softmax denominators (reduce over lanes = j) --------
#pragma unroll
    for (int ii = 0; ii < IPW; ii++)
#pragma unroll
        for (int h = 0; h < HH; h++) {
            float v = lsum[ii][h];
            v += __shfl_xor_sync(0xffffffffu, v, 16);
            v += __shfl_xor_sync(0xffffffffu, v, 8);
            v += __shfl_xor_sync(0xffffffffu, v, 4);
            v += __shfl_xor_sync(0xffffffffu, v, 2);
            v += __shfl_xor_sync(0xffffffffu, v, 1);
            lsum[ii][h] = 1.0f / v;
        }

    float gr[HH], br[HH];
#pragma unroll
    for (int h = 0; h < HH; h++) {
        gr[h] = gamma[(h << 5) + ln];
        br[h] = beta[(h << 5) + ln];
    }

    // -------- LayerNorm + ELU + store --------
    int ibase = b * NN + i0 + (w << 2);
#pragma unroll
    for (int ii = 0; ii < IPW; ii++) {
        float y[HH];
        float s = 0.f;
#pragma unroll
        for (int h = 0; h < HH; h++) { y[h] = acc[ii][h] * lsum[ii][h]; s += y[h]; }
        s += __shfl_xor_sync(0xffffffffu, s, 16);
        s += __shfl_xor_sync(0xffffffffu, s, 8);
        s += __shfl_xor_sync(0xffffffffu, s, 4);
        s += __shfl_xor_sync(0xffffffffu, s, 2);
        s += __shfl_xor_sync(0xffffffffu, s, 1);
        float mu = s * 0.00390625f;   // /256
        float vs = 0.f;
#pragma unroll
        for (int h = 0; h < HH; h++) { float d = y[h] - mu; vs = fmaf(d, d, vs); }
        vs += __shfl_xor_sync(0xffffffffu, vs, 16);
        vs += __shfl_xor_sync(0xffffffffu, vs, 8);
        vs += __shfl_xor_sync(0xffffffffu, vs, 4);
        vs += __shfl_xor_sync(0xffffffffu, vs, 2);
        vs += __shfl_xor_sync(0xffffffffu, vs, 1);
        float rstd = rsqrtf(vs * 0.00390625f + 1e-5f);
        float* op = out + (size_t)(ibase + ii) * OUTF;
#pragma unroll
        for (int h = 0; h < HH; h++) {
            float o = fmaf((y[h] - mu) * rstd, gr[h], br[h]);
            o = (o > 0.f) ? o : expm1f(o);
            op[(h << 5) + ln] = o;
        }
    }
}

// ---------------------------------------------------------------------------
extern "C" void kernel_launch(void* const* d_in, const int* in_sizes, int n_in,
                              void* d_out, int out_size) {
    const float* x     = (const float*)d_in[0];
    const int*   adj   = (const int*)  d_in[1];
    const int*   etyp  = (const int*)  d_in[2];
    const float* W     = (const float*)d_in[3];
    const float* a1    = (const float*)d_in[4];
    const float* a2    = (const float*)d_in[5];
    const float* emb   = (const float*)d_in[6];
    const float* gamma = (const float*)d_in[7];
    const float* beta  = (const float*)d_in[8];
    float* out = (float*)d_out;

    dim3 gg(OUTF / 64, (BB * NN) / 128);
    gemm_kernel<<<gg, 256>>>(x, W);
    s_kernel<<<(BB * NN * HH + 255) / 256, 256>>>(a1, a2);
    cudaFuncSetAttribute(attn_kernel, cudaFuncAttributeMaxDynamicSharedMemorySize, SMEM_BYTES);
    attn_kernel<<<BB * (NN / TI), 256, SMEM_BYTES>>>(adj, etyp, emb, gamma, beta, out);
}

// round 15
// speedup vs baseline: 1.0914x; 1.0307x over previous
#include <cuda_runtime.h>
#include <cuda_bf16.h>
#include <math.h>
#include <cstdint>

// Problem constants
#define BB 16
#define NN 512
#define INF_ 256
#define OUTF 256
#define HH 8
#define NET 50

#define TI 32   // i-rows per block (attention)
#define TJ 32   // j-cols per tile

// Scratch (device globals; no allocation allowed)
__device__ float g_Wh[BB * NN * OUTF];     // 8.4 MB
__device__ float g_s1[BB * NN * HH];
__device__ float g_s2[BB * NN * HH];

// cp.async helpers (LDGSTS on sm_103a)
#define CP_ASYNC16(dst_u32, src) \
    asm volatile("cp.async.cg.shared.global [%0], [%1], 16;\n" :: "r"(dst_u32), "l"(src))
#define CP_COMMIT() asm volatile("cp.async.commit_group;\n")
#define CP_WAIT1()  asm volatile("cp.async.wait_group 1;\n")
#define CP_WAIT0()  asm volatile("cp.async.wait_group 0;\n")

// packed f32x2 FMA (FFMA2 — sm_103a, only reachable via PTX)
#define FMA_F32X2(d, a, b, c) \
    asm("fma.rn.f32x2 %0, %1, %2, %3;" : "=l"(d) : "l"(a), "l"(b), "l"(c))
#define PACK2(d, lo, hi) \
    asm("mov.b64 %0, {%1, %2};" : "=l"(d) : "f"(lo), "f"(hi))
#define UNPACK2(lo, hi, s) \
    asm("mov.b64 {%0, %1}, %2;" : "=f"(lo), "=f"(hi) : "l"(s))
#define LDS_V2U64(q0, q1, addr) \
    asm volatile("ld.shared.v2.u64 {%0, %1}, [%2];" : "=l"(q0), "=l"(q1) : "r"(addr))

// ---------------------------------------------------------------------------
// Kernel A: Wh = x @ W   (M=8192, K=256, N=256). 128x64 tile, 8x4 microtile.
// At fp32 FMA roofline (ncu: ~32us) — unchanged.
// ---------------------------------------------------------------------------
__global__ __launch_bounds__(256) void gemm_kernel(const float* __restrict__ x,
                                                   const float* __restrict__ W) {
    __shared__ float sA[16][132];
    __shared__ float sB[16][64];
    int tid = threadIdx.x;
    int row0 = blockIdx.y * 128;
    int col0 = blockIdx.x * 64;
    int tx = tid & 15, ty = tid >> 4;

    int ar = tid >> 2;
    int ac4 = (tid & 3) << 2;
    int br = tid >> 4;
    int bc4 = (tid & 15) << 2;

    float acc0[4][4] = {}, acc1[4][4] = {};
    float4 pa0, pa1, pb;

    pa0 = *(const float4*)(x + (size_t)(row0 + ar) * INF_ + ac4);
    pa1 = *(const float4*)(x + (size_t)(row0 + 64 + ar) * INF_ + ac4);
    pb  = *(const float4*)(W + (size_t)br * OUTF + col0 + bc4);

    for (int kt = 0; kt < 16; kt++) {
        __syncthreads();
        sA[ac4 + 0][ar] = pa0.x; sA[ac4 + 1][ar] = pa0.y;
        sA[ac4 + 2][ar] = pa0.z; sA[ac4 + 3][ar] = pa0.w;
        sA[ac4 + 0][64 + ar] = pa1.x; sA[ac4 + 1][64 + ar] = pa1.y;
        sA[ac4 + 2][64 + ar] = pa1.z; sA[ac4 + 3][64 + ar] = pa1.w;
        *(float4*)&sB[br][bc4] = pb;
        __syncthreads();
        if (kt < 15) {
            int k0 = (kt + 1) * 16;
            pa0 = *(const float4*)(x + (size_t)(row0 + ar) * INF_ + k0 + ac4);
            pa1 = *(const float4*)(x + (size_t)(row0 + 64 + ar) * INF_ + k0 + ac4);
            pb  = *(const float4*)(W + (size_t)(k0 + br) * OUTF + col0 + bc4);
        }
#pragma unroll
        for (int k = 0; k < 16; k++) {
            float4 aL = *(const float4*)(&sA[k][ty << 2]);
            float4 aH = *(const float4*)(&sA[k][64 + (ty << 2)]);
            float4 b  = *(const float4*)(&sB[k][tx << 2]);
            float av[4] = {aL.x, aL.y, aL.z, aL.w};
            float ah[4] = {aH.x, aH.y, aH.z, aH.w};
            float bv[4] = {b.x, b.y, b.z, b.w};
#pragma unroll
            for (int i = 0; i < 4; i++)
#pragma unroll
                for (int j = 0; j < 4; j++) {
                    acc0[i][j] = fmaf(av[i], bv[j], acc0[i][j]);
                    acc1[i][j] = fmaf(ah[i], bv[j], acc1[i][j]);
                }
        }
    }
#pragma unroll
    for (int i = 0; i < 4; i++) {
        float4 v0 = make_float4(acc0[i][0], acc0[i][1], acc0[i][2], acc0[i][3]);
        float4 v1 = make_float4(acc1[i][0], acc1[i][1], acc1[i][2], acc1[i][3]);
        *(float4*)(g_Wh + (size_t)(row0 + (ty << 2) + i) * OUTF + col0 + (tx << 2)) = v0;
        *(float4*)(g_Wh + (size_t)(row0 + 64 + (ty << 2) + i) * OUTF + col0 + (tx << 2)) = v1;
    }
}

// ---------------------------------------------------------------------------
// Kernel B: s1/s2 projections. One thread per (n,h).
// ---------------------------------------------------------------------------
__global__ __launch_bounds__(256) void s_kernel(const float* __restrict__ a1,
                                                const float* __restrict__ a2) {
    int t = blockIdx.x * blockDim.x + threadIdx.x;
    if (t >= BB * NN * HH) return;
    int h = t & 7;
    int n = t >> 3;
    const float4* row = (const float4*)(g_Wh + (size_t)n * OUTF + h * 32);
    const float4* A1 = (const float4*)a1;
    const float4* A2 = (const float4*)a2;
    float t1 = 0.f, t2 = 0.f;
#pragma unroll
    for (int d4 = 0; d4 < 8; d4++) {
        float4 v = row[d4];
        float4 w1 = A1[d4];
        float4 w2 = A2[d4];
        t1 = fmaf(v.x, w1.x, t1); t1 = fmaf(v.y, w1.y, t1);
        t1 = fmaf(v.z, w1.z, t1); t1 = fmaf(v.w, w1.w, t1);
        t2 = fmaf(v.x, w2.x, t2); t2 = fmaf(v.y, w2.y, t2);
        t2 = fmaf(v.z, w2.z, t2); t2 = fmaf(v.w, w2.w, t2);
    }
    g_s1[t] = t1;
    g_s2[t] = t2;
}

// ---------------------------------------------------------------------------
// Kernel C: fused attention, 512 threads. Warp (wl = w&7, wg = w>>3):
// wl picks 4 i-rows (il = 4*wl+ii), wg picks 4 heads (h = 4*wg+hh).
// Per-tile: score(lane=j) -> STS.128 -> syncwarp -> FFMA2 accumulate(lane=d).
// Wh + adj + et double-buffered via cp.async.
// ---------------------------------------------------------------------------
#define SM_WH   0                   // 2 x 8192 f
#define SM_P    16384               // 16 warps x 2 slots x 32j x 4ii = 4096 f
#define SM_ADJ  20480               // 2 x 1024 i
#define SM_ET   22528               // 2 x 1024 i
#define SM_S2   24576               // 288 f (32 x stride 9)
#define SM_S1   24864               // 256 f
#define SM_EMB  25120               // 450 f (50 x stride 9)
#define SMEM_FLOATS 25572
#define SMEM_BYTES (SMEM_FLOATS * 4)    // 102288 B -> 2 blocks/SM

__global__ __launch_bounds__(512, 2)
void attn_kernel(const int* __restrict__ adj, const int* __restrict__ et,
                 const float* __restrict__ emb, const float* __restrict__ gamma,
                 const float* __restrict__ beta, float* __restrict__ out) {
    extern __shared__ float sm[];
    float* sWh  = sm + SM_WH;       // [2][8192]
    float* sP   = sm + SM_P;        // [16 warps][2 slots][32j][4ii]
    int*   sAdj = (int*)(sm + SM_ADJ);  // [2][1024]
    int*   sEt  = (int*)(sm + SM_ET);   // [2][1024]
    float* sS2  = sm + SM_S2;
    float* sS1  = sm + SM_S1;
    float* sEmb = sm + SM_EMB;

    int tid = threadIdx.x;
    int w = tid >> 5, ln = tid & 31;
    int wl = w & 7;                 // i-row group: il = 4*wl + ii
    int hbase = (w >> 3) << 2;      // head group: h = hbase + hh
    int b  = blockIdx.x >> 4;
    int i0 = (blockIdx.x & 15) * TI;

    if (tid < 256) sS1[tid] = g_s1[(size_t)(b * NN + i0) * HH + tid];
    if (tid < NET * HH) sEmb[(tid >> 3) * 9 + (tid & 7)] = emb[tid];

    const float* gWhB = g_Wh + (size_t)b * NN * OUTF;
    const int* adjB = adj + (size_t)(b * NN + i0) * NN;
    const int* etB  = et  + (size_t)(b * NN + i0) * NN;
    unsigned int swhA  = (unsigned int)__cvta_generic_to_shared(sWh);
    unsigned int sadjA = (unsigned int)__cvta_generic_to_shared(sAdj);
    unsigned int setA  = (unsigned int)__cvta_generic_to_shared(sEt);
    float* sPw = sP + (w << 8);                 // 256 f per warp
    unsigned int spA = (unsigned int)__cvta_generic_to_shared(sPw);

    // staging index maps for adj/et (16B chunks: 256 per array)
    int sr = (tid & 255) >> 3;      // row 0..31
    int sc = (tid & 7) << 2;        // col chunk (4 ints)

    // ---- prologue: group 0 = Wh tile 0 + adj/et tile 0 ----
#pragma unroll
    for (int q = 0; q < 4; q++) {
        unsigned int off = (unsigned int)(q * 512 + tid) * 16u;
        CP_ASYNC16(swhA + off, (const char*)gWhB + off);
    }
    if (tid < 256) {
        CP_ASYNC16(sadjA + (unsigned int)(tid << 4), adjB + sr * NN + sc);
    } else {
        CP_ASYNC16(setA + (unsigned int)((tid - 256) << 4), etB + sr * NN + sc);
    }
    CP_COMMIT();

    float s2R = (tid < 256) ? g_s2[(size_t)b * NN * HH + tid] : 0.f;

    unsigned long long acc01[4], acc23[4];      // f32x2 accumulators per hh
    float lsum[4][4];                            // [ii][hh]
#pragma unroll
    for (int hh = 0; hh < 4; hh++) { acc01[hh] = 0ull; acc23[hh] = 0ull; }
#pragma unroll
    for (int ii = 0; ii < 4; ii++)
#pragma unroll
        for (int hh = 0; hh < 4; hh++) lsum[ii][hh] = 0.f;

    for (int jt = 0; jt < NN / TJ; jt++) {
        int cur = jt & 1;
        __syncthreads();
        if (tid < 256) sS2[(tid >> 3) * 9 + (tid & 7)] = s2R;
        if (jt < 15) {
            int j0n = (jt + 1) * TJ;
            unsigned int dwh = swhA + (unsigned int)(cur ^ 1) * 32768u;
            const char* srcW = (const char*)gWhB + (size_t)(jt + 1) * 32768u;
#pragma unroll
            for (int q = 0; q < 4; q++) {
                unsigned int off = (unsigned int)(q * 512 + tid) * 16u;
                CP_ASYNC16(dwh + off, srcW + off);
            }
            if (tid < 256) {
                CP_ASYNC16(sadjA + (unsigned int)(cur ^ 1) * 4096u + (unsigned int)(tid << 4),
                           adjB + sr * NN + j0n + sc);
            } else {
                CP_ASYNC16(setA + (unsigned int)(cur ^ 1) * 4096u + (unsigned int)((tid - 256) << 4),
                           etB + sr * NN + j0n + sc);
            }
            CP_COMMIT();
            CP_WAIT1();
        } else {
            CP_WAIT0();
        }
        __syncthreads();
        if (jt < 15 && tid < 256)
            s2R = g_s2[(size_t)b * NN * HH + (size_t)(jt + 1) * TJ * HH + tid];

        // hoist per-tile: adjacency + emb row per ii (lane = j)
        const int* aCur = sAdj + cur * 1024;
        const int* eCur = sEt  + cur * 1024;
        int adjv[4], ebi[4];
#pragma unroll
        for (int ii = 0; ii < 4; ii++) {
            int il = (wl << 2) + ii;
            adjv[ii] = aCur[(il << 5) + ln];
            ebi[ii]  = eCur[(il << 5) + ln] * 9;
        }

        const float* whB = sWh + cur * 8192;
#pragma unroll
        for (int hh = 0; hh < 4; hh++) {
            int h = hbase + hh;
            // ---- score (lane = j): p[4ii] in regs, one STS.128 ----
            float s2v = sS2[ln * 9 + h];
            float pv[4];
#pragma unroll
            for (int ii = 0; ii < 4; ii++) {
                int il = (wl << 2) + ii;
                float e = sS1[(il << 3) + h] + s2v + sEmb[ebi[ii] + h];
                e = fmaf(0.2f, fminf(e, 0.f), fmaxf(e, 0.f));   // leaky relu 0.2
                float p = (adjv[ii] != 0) ? __expf(e) : 0.0f;   // |e|<~12: safe
                lsum[ii][hh] += p;
                pv[ii] = p;
            }
            *(float4*)(sPw + ((h & 1) << 7) + (ln << 2)) =
                make_float4(pv[0], pv[1], pv[2], pv[3]);
            __syncwarp();   // cross-lane RAW on this warp's sP slot

            // ---- accumulate (lane = d): FFMA2 over ii pairs ----
            const float* whc = whB + (h << 5) + ln;
            unsigned int rowA = spA + (unsigned int)((h & 1) << 9);
#pragma unroll 8
            for (int j = 0; j < 32; j++) {
                unsigned long long q01, q23, ww;
                LDS_V2U64(q01, q23, rowA + (unsigned int)(j << 4));
                float wv = whc[j * OUTF];
                PACK2(ww, wv, wv);
                FMA_F32X2(acc01[hh], q01, ww, acc01[hh]);
                FMA_F32X2(acc23[hh], q23, ww, acc23[hh]);
            }
        }
    }

    // -------- softmax denominators (reduce over lanes = j) --------
#pragma unroll
    for (int ii = 0; ii < 4; ii++)
#pragma unroll
        for (int hh = 0; hh < 4; hh++) {
            float v = lsum[ii][hh];
            v += __shfl_xor_sync(0xffffffffu, v, 16);
            v += __shfl_xor_sync(0xffffffffu, v, 8);
            v += __shfl_xor_sync(0xffffffffu, v, 4);
            v += __shfl_xor_sync(0xffffffffu, v, 2);
            v += __shfl_xor_sync(0xffffffffu, v, 1);
            lsum[ii][hh] = 1.0f / v;
        }

    // -------- stage normalized y into sOut (dead Wh buffer 0) --------
    float* sOut = sWh;   // 8192 f: [32 rows][256 feats]
#pragma unroll
    for (int hh = 0; hh < 4; hh++) {
        int h = hbase + hh;
        float y0, y1, y2, y3;
        UNPACK2(y0, y1, acc01[hh]);
        UNPACK2(y2, y3, acc23[hh]);
        y0 *= lsum[0][hh]; y1 *= lsum[1][hh];
        y2 *= lsum[2][hh]; y3 *= lsum[3][hh];
        int base = (h << 5) + ln;
        sOut[(((wl << 2) + 0) << 8) + base] = y0;
        sOut[(((wl << 2) + 1) << 8) + base] = y1;
        sOut[(((wl << 2) + 2) << 8) + base] = y2;
        sOut[(((wl << 2) + 3) << 8) + base] = y3;
    }
    __syncthreads();

    // -------- LayerNorm + ELU + store: warp w handles rows 2w, 2w+1 --------
#pragma unroll
    for (int r2 = 0; r2 < 2; r2++) {
        int r = (w << 1) + r2;
        float y[HH];
        float s = 0.f;
#pragma unroll
        for (int h = 0; h < HH; h++) { y[h] = sOut[(r << 8) + (h << 5) + ln]; s += y[h]; }
        s += __shfl_xor_sync(0xffffffffu, s, 16);
        s += __shfl_xor_sync(0xffffffffu, s, 8);
        s += __shfl_xor_sync(0xffffffffu, s, 4);
        s += __shfl_xor_sync(0xffffffffu, s, 2);
        s += __shfl_xor_sync(0xffffffffu, s, 1);
        float mu = s * 0.00390625f;   // /256
        float vs = 0.f;
#pragma unroll
        for (int h = 0; h < HH; h++) { float d = y[h] - mu; vs = fmaf(d, d, vs); }
        vs += __shfl_xor_sync(0xffffffffu, vs, 16);
        vs += __shfl_xor_sync(0xffffffffu, vs, 8);
        vs += __shfl_xor_sync(0xffffffffu, vs, 4);
        vs += __shfl_xor_sync(0xffffffffu, vs, 2);
        vs += __shfl_xor_sync(0xffffffffu, vs, 1);
        float rstd = rsqrtf(vs * 0.00390625f + 1e-5f);
        float* op = out + (size_t)(b * NN + i0 + r) * OUTF;
#pragma unroll
        for (int h = 0; h < HH; h++) {
            float o = fmaf((y[h] - mu) * rstd, gamma[(h << 5) + ln], beta[(h << 5) + ln]);
            o = (o > 0.f) ? o : expm1f(o);
            op[(h << 5) + ln] = o;
        }
    }
}

// ---------------------------------------------------------------------------
extern "C" void kernel_launch(void* const* d_in, const int* in_sizes, int n_in,
                              void* d_out, int out_size) {
    const float* x     = (const float*)d_in[0];
    const int*   adj   = (const int*)  d_in[1];
    const int*   etyp  = (const int*)  d_in[2];
    const float* W     = (const float*)d_in[3];
    const float* a1    = (const float*)d_in[4];
    const float* a2    = (const float*)d_in[5];
    const float* emb   = (const float*)d_in[6];
    const float* gamma = (const float*)d_in[7];
    const float* beta  = (const float*)d_in[8];
    float* out = (float*)d_out;

    dim3 gg(OUTF / 64, (BB * NN) / 128);
    gemm_kernel<<<gg, 256>>>(x, W);
    s_kernel<<<(BB * NN * HH + 255) / 256, 256>>>(a1, a2);
    cudaFuncSetAttribute(attn_kernel, cudaFuncAttributeMaxDynamicSharedMemorySize, SMEM_BYTES);
    attn_kernel<<<BB * (NN / TI), 512, SMEM_BYTES>>>(adj, etyp, emb, gamma, beta, out);
}

// round 16
// speedup vs baseline: 1.2017x; 1.1011x over previous
#include <cuda_runtime.h>
#include <cuda_bf16.h>
#include <math.h>
#include <cstdint>

// Problem constants
#define BB 16
#define NN 512
#define INF_ 256
#define OUTF 256
#define HH 8
#define NET 50

#define TI 32   // i-rows per block (attention)
#define TJ 32   // j-cols per tile

// Scratch (device globals; no allocation allowed)
__device__ float g_Wh[BB * NN * OUTF];     // 8.4 MB
__device__ float g_s1[BB * NN * HH];
__device__ float g_s2[BB * NN * HH];

// cp.async helpers (LDGSTS on sm_103a)
#define CP_ASYNC16(dst_u32, src) \
    asm volatile("cp.async.cg.shared.global [%0], [%1], 16;\n" :: "r"(dst_u32), "l"(src))
#define CP_COMMIT() asm volatile("cp.async.commit_group;\n")
#define CP_WAIT1()  asm volatile("cp.async.wait_group 1;\n")
#define CP_WAIT0()  asm volatile("cp.async.wait_group 0;\n")

// packed f32x2 ops (sm_103a)
#define FMA_F32X2(d, a, b, c) \
    asm("fma.rn.f32x2 %0, %1, %2, %3;" : "=l"(d) : "l"(a), "l"(b), "l"(c))
#define ADD_F32X2(d, a, b) \
    asm("add.rn.f32x2 %0, %1, %2;" : "=l"(d) : "l"(a), "l"(b))
#define PACK2(d, lo, hi) \
    asm("mov.b64 %0, {%1, %2};" : "=l"(d) : "f"(lo), "f"(hi))
#define UNPACK2(lo, hi, s) \
    asm("mov.b64 {%0, %1}, %2;" : "=f"(lo), "=f"(hi) : "l"(s))
#define LDS_V2U64(q0, q1, addr) \
    asm volatile("ld.shared.v2.u64 {%0, %1}, [%2];" : "=l"(q0), "=l"(q1) : "r"(addr))

// ---------------------------------------------------------------------------
// Kernel A: Wh = x @ W  (at fp32 FMA roofline per ncu — unchanged)
// ---------------------------------------------------------------------------
__global__ __launch_bounds__(256) void gemm_kernel(const float* __restrict__ x,
                                                   const float* __restrict__ W) {
    __shared__ float sA[16][132];
    __shared__ float sB[16][64];
    int tid = threadIdx.x;
    int row0 = blockIdx.y * 128;
    int col0 = blockIdx.x * 64;
    int tx = tid & 15, ty = tid >> 4;

    int ar = tid >> 2;
    int ac4 = (tid & 3) << 2;
    int br = tid >> 4;
    int bc4 = (tid & 15) << 2;

    float acc0[4][4] = {}, acc1[4][4] = {};
    float4 pa0, pa1, pb;

    pa0 = *(const float4*)(x + (size_t)(row0 + ar) * INF_ + ac4);
    pa1 = *(const float4*)(x + (size_t)(row0 + 64 + ar) * INF_ + ac4);
    pb  = *(const float4*)(W + (size_t)br * OUTF + col0 + bc4);

    for (int kt = 0; kt < 16; kt++) {
        __syncthreads();
        sA[ac4 + 0][ar] = pa0.x; sA[ac4 + 1][ar] = pa0.y;
        sA[ac4 + 2][ar] = pa0.z; sA[ac4 + 3][ar] = pa0.w;
        sA[ac4 + 0][64 + ar] = pa1.x; sA[ac4 + 1][64 + ar] = pa1.y;
        sA[ac4 + 2][64 + ar] = pa1.z; sA[ac4 + 3][64 + ar] = pa1.w;
        *(float4*)&sB[br][bc4] = pb;
        __syncthreads();
        if (kt < 15) {
            int k0 = (kt + 1) * 16;
            pa0 = *(const float4*)(x + (size_t)(row0 + ar) * INF_ + k0 + ac4);
            pa1 = *(const float4*)(x + (size_t)(row0 + 64 + ar) * INF_ + k0 + ac4);
            pb  = *(const float4*)(W + (size_t)(k0 + br) * OUTF + col0 + bc4);
        }
#pragma unroll
        for (int k = 0; k < 16; k++) {
            float4 aL = *(const float4*)(&sA[k][ty << 2]);
            float4 aH = *(const float4*)(&sA[k][64 + (ty << 2)]);
            float4 b  = *(const float4*)(&sB[k][tx << 2]);
            float av[4] = {aL.x, aL.y, aL.z, aL.w};
            float ah[4] = {aH.x, aH.y, aH.z, aH.w};
            float bv[4] = {b.x, b.y, b.z, b.w};
#pragma unroll
            for (int i = 0; i < 4; i++)
#pragma unroll
                for (int j = 0; j < 4; j++) {
                    acc0[i][j] = fmaf(av[i], bv[j], acc0[i][j]);
                    acc1[i][j] = fmaf(ah[i], bv[j], acc1[i][j]);
                }
        }
    }
#pragma unroll
    for (int i = 0; i < 4; i++) {
        float4 v0 = make_float4(acc0[i][0], acc0[i][1], acc0[i][2], acc0[i][3]);
        float4 v1 = make_float4(acc1[i][0], acc1[i][1], acc1[i][2], acc1[i][3]);
        *(float4*)(g_Wh + (size_t)(row0 + (ty << 2) + i) * OUTF + col0 + (tx << 2)) = v0;
        *(float4*)(g_Wh + (size_t)(row0 + 64 + (ty << 2) + i) * OUTF + col0 + (tx << 2)) = v1;
    }
}

// ---------------------------------------------------------------------------
// Kernel B: s1/s2 projections. One thread per (n,h).
// ---------------------------------------------------------------------------
__global__ __launch_bounds__(256) void s_kernel(const float* __restrict__ a1,
                                                const float* __restrict__ a2) {
    int t = blockIdx.x * blockDim.x + threadIdx.x;
    if (t >= BB * NN * HH) return;
    int h = t & 7;
    int n = t >> 3;
    const float4* row = (const float4*)(g_Wh + (size_t)n * OUTF + h * 32);
    const float4* A1 = (const float4*)a1;
    const float4* A2 = (const float4*)a2;
    float t1 = 0.f, t2 = 0.f;
#pragma unroll
    for (int d4 = 0; d4 < 8; d4++) {
        float4 v = row[d4];
        float4 w1 = A1[d4];
        float4 w2 = A2[d4];
        t1 = fmaf(v.x, w1.x, t1); t1 = fmaf(v.y, w1.y, t1);
        t1 = fmaf(v.z, w1.z, t1); t1 = fmaf(v.w, w1.w, t1);
        t2 = fmaf(v.x, w2.x, t2); t2 = fmaf(v.y, w2.y, t2);
        t2 = fmaf(v.z, w2.z, t2); t2 = fmaf(v.w, w2.w, t2);
    }
    g_s1[t] = t1;
    g_s2[t] = t2;
}

// ---------------------------------------------------------------------------
// Kernel C: fused attention, 512 threads, 16 warps.
// Warp w: ig = w>>3 (i-group: rows ig*16..+15), h = w&7 (one head).
// Only 2 warps share each head -> Wh LDS traffic cut 4x vs R15.
// Per tile: score(lane=j) -> 4 swizzled STS.128 -> 1 syncwarp ->
//           accumulate(lane=d): per j: 1 Wh LDS + 4 p-broadcast LDS + 8 FFMA2.
// sP single-slot per warp (2KB); reuse guarded by loop-top __syncthreads.
// ---------------------------------------------------------------------------
#define SM_WH   0                   // 2 x 8192 f (double-buffered Wh tiles)
#define SM_P    16384               // 16 warps x 512 f (32j x 16ii, swizzled)
#define SM_CODE 24576               // 1024 i: adj/et fused (-1 masked, else et*9)
#define SM_S2   25600               // 288 f (32 x stride 9)
#define SM_S1   25888               // 256 f
#define SM_EMB  26144               // 450 f (50 x stride 9)
#define SMEM_FLOATS 26594
#define SMEM_BYTES (SMEM_FLOATS * 4)    // 106376 B -> 2 blocks/SM

__global__ __launch_bounds__(512, 2)
void attn_kernel(const int* __restrict__ adj, const int* __restrict__ et,
                 const float* __restrict__ emb, const float* __restrict__ gamma,
                 const float* __restrict__ beta, float* __restrict__ out) {
    extern __shared__ float sm[];
    float* sWh   = sm + SM_WH;      // [2][8192]
    float* sP    = sm + SM_P;       // [16 warps][512]
    int*   sCode = (int*)(sm + SM_CODE);
    float* sS2   = sm + SM_S2;
    float* sS1   = sm + SM_S1;
    float* sEmb  = sm + SM_EMB;

    int tid = threadIdx.x;
    int w = tid >> 5, ln = tid & 31;
    int ig = w >> 3;                // i-group: rows ig*16 .. ig*16+15
    int h  = w & 7;                 // this warp's head
    int b  = blockIdx.x >> 4;
    int i0 = (blockIdx.x & 15) * TI;

    if (tid < 256) sS1[tid] = g_s1[(size_t)(b * NN + i0) * HH + tid];
    if (tid < NET * HH) sEmb[(tid >> 3) * 9 + (tid & 7)] = emb[tid];

    const float* gWhB = g_Wh + (size_t)b * NN * OUTF;
    const int* adjB = adj + (size_t)(b * NN + i0) * NN;
    const int* etB  = et  + (size_t)(b * NN + i0) * NN;
    unsigned int swhA = (unsigned int)__cvta_generic_to_shared(sWh);
    float* sPw = sP + (w << 9);                  // 512 floats per warp
    unsigned int spA = (unsigned int)__cvta_generic_to_shared(sPw);

    // ---- prologue: Wh tile 0 via cp.async ----
#pragma unroll
    for (int q = 0; q < 4; q++) {
        unsigned int off = (unsigned int)(q * 512 + tid) * 16u;
        CP_ASYNC16(swhA + off, (const char*)gWhB + off);
    }
    CP_COMMIT();

    // ---- prefetch adj/et (2 cells per thread) + s2 for tile 0 ----
    int cr = tid >> 4;              // row 0..31
    int cc = (tid & 15) << 1;       // col 0,2,..30
    int2 adjR = *(const int2*)(adjB + cr * NN + cc);
    int2 etR  = *(const int2*)(etB  + cr * NN + cc);
    float s2R = (tid < 256) ? g_s2[(size_t)b * NN * HH + tid] : 0.f;

    unsigned long long acc[8], lsum2[8];   // f32x2: ii pairs (chunk q -> 2q,2q+1)
#pragma unroll
    for (int k = 0; k < 8; k++) { acc[k] = 0ull; lsum2[k] = 0ull; }

    for (int jt = 0; jt < NN / TJ; jt++) {
        int cur = jt & 1;
        __syncthreads();            // all warps done reading sCode/sS2 (+ sP reuse safe)
        // stage fused code + s2
        {
            int2 code;
            code.x = adjR.x ? etR.x * 9 : -1;
            code.y = adjR.y ? etR.y * 9 : -1;
            *(int2*)(sCode + cr * 32 + cc) = code;
        }
        if (tid < 256) sS2[(tid >> 3) * 9 + (tid & 7)] = s2R;
        // async Wh for next tile
        if (jt < 15) {
            unsigned int dwh = swhA + (unsigned int)(cur ^ 1) * 32768u;
            const char* srcW = (const char*)gWhB + (size_t)(jt + 1) * 32768u;
#pragma unroll
            for (int q = 0; q < 4; q++) {
                unsigned int off = (unsigned int)(q * 512 + tid) * 16u;
                CP_ASYNC16(dwh + off, srcW + off);
            }
            CP_COMMIT();
            CP_WAIT1();
        } else {
            CP_WAIT0();
        }
        __syncthreads();            // sCode/sS2/sWh[cur] visible
        // prefetch next tile's adj/et/s2 (overlaps compute)
        if (jt < 15) {
            int j0n = (jt + 1) * TJ;
            adjR = *(const int2*)(adjB + cr * NN + j0n + cc);
            etR  = *(const int2*)(etB  + cr * NN + j0n + cc);
            if (tid < 256)
                s2R = g_s2[(size_t)b * NN * HH + (size_t)j0n * HH + tid];
        }

        // -------- score phase (lane = j): 16 ii, one head --------
        float s2v = sS2[ln * 9 + h];
#pragma unroll
        for (int q = 0; q < 4; q++) {
            float4 pv;
            float* pvp = &pv.x;
#pragma unroll
            for (int k = 0; k < 4; k++) {
                int il = (ig << 4) + (q << 2) + k;
                int code = sCode[(il << 5) + ln];
                float p = 0.f;
                if (code >= 0) {
                    float e = sS1[(il << 3) + h] + s2v + sEmb[code + h];
                    e = fmaf(0.2f, fminf(e, 0.f), fmaxf(e, 0.f));   // leaky relu
                    p = __expf(e);                                  // |e|<~12: safe
                }
                pvp[k] = p;
            }
            unsigned long long t01, t23;
            PACK2(t01, pv.x, pv.y); ADD_F32X2(lsum2[2 * q], lsum2[2 * q], t01);
            PACK2(t23, pv.z, pv.w); ADD_F32X2(lsum2[2 * q + 1], lsum2[2 * q + 1], t23);
            int c = (q + (ln >> 2)) & 3;           // conflict-free swizzle
            *(float4*)(sPw + (ln << 4) + (c << 2)) = pv;
        }
        __syncwarp();   // sP slot: cross-lane RAW

        // -------- accumulate phase (lane = d): FFMA2 --------
        const float* whc = sWh + cur * 8192 + (h << 5) + ln;
#pragma unroll 4
        for (int j = 0; j < 32; j++) {
            float wv = whc[j * OUTF];
            unsigned long long ww;
            PACK2(ww, wv, wv);
            unsigned int jb = spA + (unsigned int)(j << 6);
            int js = j >> 2;
#pragma unroll
            for (int q = 0; q < 4; q++) {
                unsigned long long q01, q23;
                LDS_V2U64(q01, q23, jb + (unsigned int)(((q + js) & 3) << 4));
                FMA_F32X2(acc[2 * q], q01, ww, acc[2 * q]);
                FMA_F32X2(acc[2 * q + 1], q23, ww, acc[2 * q + 1]);
            }
        }
    }

    // -------- softmax denominators: reduce lsum2 over lanes (f32x2-wise) --------
#pragma unroll
    for (int k = 0; k < 8; k++) {
        unsigned long long v = lsum2[k];
#pragma unroll
        for (int m = 16; m >= 1; m >>= 1) {
            unsigned long long o = __shfl_xor_sync(0xffffffffu, v, m);
            ADD_F32X2(v, v, o);
        }
        lsum2[k] = v;
    }

    // -------- stage normalized y into sOut (dead Wh buffer 0) --------
    float* sOut = sWh;   // 8192 f: [32 rows][256 feats]
#pragma unroll
    for (int q = 0; q < 4; q++) {
        float l0, l1, l2, l3, y0, y1, y2, y3;
        UNPACK2(l0, l1, lsum2[2 * q]);
        UNPACK2(l2, l3, lsum2[2 * q + 1]);
        UNPACK2(y0, y1, acc[2 * q]);
        UNPACK2(y2, y3, acc[2 * q + 1]);
        int il = (ig << 4) + (q << 2);
        int base = (h << 5) + ln;
        sOut[((il + 0) << 8) + base] = y0 / l0;
        sOut[((il + 1) << 8) + base] = y1 / l1;
        sOut[((il + 2) << 8) + base] = y2 / l2;
        sOut[((il + 3) << 8) + base] = y3 / l3;
    }
    __syncthreads();

    // -------- LayerNorm + ELU + store: warp w handles rows 2w, 2w+1 --------
#pragma unroll
    for (int r2 = 0; r2 < 2; r2++) {
        int r = (w << 1) + r2;
        float y[HH];
        float s = 0.f;
#pragma unroll
        for (int hq = 0; hq < HH; hq++) { y[hq] = sOut[(r << 8) + (hq << 5) + ln]; s += y[hq]; }
        s += __shfl_xor_sync(0xffffffffu, s, 16);
        s += __shfl_xor_sync(0xffffffffu, s, 8);
        s += __shfl_xor_sync(0xffffffffu, s, 4);
        s += __shfl_xor_sync(0xffffffffu, s, 2);
        s += __shfl_xor_sync(0xffffffffu, s, 1);
        float mu = s * 0.00390625f;   // /256
        float vs = 0.f;
#pragma unroll
        for (int hq = 0; hq < HH; hq++) { float d = y[hq] - mu; vs = fmaf(d, d, vs); }
        vs += __shfl_xor_sync(0xffffffffu, vs, 16);
        vs += __shfl_xor_sync(0xffffffffu, vs, 8);
        vs += __shfl_xor_sync(0xffffffffu, vs, 4);
        vs += __shfl_xor_sync(0xffffffffu, vs, 2);
        vs += __shfl_xor_sync(0xffffffffu, vs, 1);
        float rstd = rsqrtf(vs * 0.00390625f + 1e-5f);
        float* op = out + (size_t)(b * NN + i0 + r) * OUTF;
#pragma unroll
        for (int hq = 0; hq < HH; hq++) {
            float o = fmaf((y[hq] - mu) * rstd, gamma[(hq << 5) + ln], beta[(hq << 5) + ln]);
            o = (o > 0.f) ? o : expm1f(o);
            op[(hq << 5) + ln] = o;
        }
    }
}

// ---------------------------------------------------------------------------
extern "C" void kernel_launch(void* const* d_in, const int* in_sizes, int n_in,
                              void* d_out, int out_size) {
    const float* x     = (const float*)d_in[0];
    const int*   adj   = (const int*)  d_in[1];
    const int*   etyp  = (const int*)  d_in[2];
    const float* W     = (const float*)d_in[3];
    const float* a1    = (const float*)d_in[4];
    const float* a2    = (const float*)d_in[5];
    const float* emb   = (const float*)d_in[6];
    const float* gamma = (const float*)d_in[7];
    const float* beta  = (const float*)d_in[8];
    float* out = (float*)d_out;

    dim3 gg(OUTF / 64, (BB * NN) / 128);
    gemm_kernel<<<gg, 256>>>(x, W);
    s_kernel<<<(BB * NN * HH + 255) / 256, 256>>>(a1, a2);
    cudaFuncSetAttribute(attn_kernel, cudaFuncAttributeMaxDynamicSharedMemorySize, SMEM_BYTES);
    attn_kernel<<<BB * (NN / TI), 512, SMEM_BYTES>>>(adj, etyp, emb, gamma, beta, out);
}